// round 3
// baseline (speedup 1.0000x reference)
#include <cuda_runtime.h>

#define G_NODES 100000
#define IN_DIM  256
#define OUT_DIM 128
#define B_ROWS  4096
#define N_COLS  8192
#define ALPHA   0.2f

// ---------------- device scratch (static, allocation-free) ----------------
__device__ __align__(16) float g_hneigh[N_COLS * OUT_DIM]; // [8192][128] fp32
__device__ float g_s2[N_COLS];
__device__ float g_p[N_COLS];
__device__ float g_q[N_COLS];
__device__ float g_t[B_ROWS];   // -s1[b]
__device__ float g_P[B_ROWS];
__device__ float g_Q[B_ROWS];
__device__ float g_Wa1[IN_DIM];
__device__ float g_S2max;

// ---------------- packed f32x2 helpers (FFMA2) ----------------
__device__ __forceinline__ unsigned long long fma2(unsigned long long a,
                                                   unsigned long long b,
                                                   unsigned long long c) {
    unsigned long long d;
    asm("fma.rn.f32x2 %0, %1, %2, %3;" : "=l"(d) : "l"(a), "l"(b), "l"(c));
    return d;
}
__device__ __forceinline__ unsigned long long pk2(float lo, float hi) {
    unsigned long long r;
    asm("mov.b64 %0, {%1, %2};" : "=l"(r) : "f"(lo), "f"(hi));
    return r;
}
__device__ __forceinline__ void upk2(unsigned long long v, float& lo, float& hi) {
    asm("mov.b64 {%0, %1}, %2;" : "=f"(lo), "=f"(hi) : "l"(v));
}

// ---------------- K0: Wa1[k] = sum_c W[k][c] * a1[c] ----------------
__global__ void k_wa1(const float* __restrict__ W, const float* __restrict__ a1) {
    int k = threadIdx.x;  // 256 threads
    const float* row = W + k * OUT_DIM;
    float s = 0.f;
#pragma unroll 8
    for (int c = 0; c < OUT_DIM; c++) s += row[c] * a1[c];
    g_Wa1[k] = s;
}

// ---------------- K1: h_neigh = gf[unique_nodes] @ W ; s2 = h_neigh @ a2 ----
__global__ __launch_bounds__(256) void k_hneigh(
    const float* __restrict__ gf, const int* __restrict__ un,
    const float* __restrict__ W, const float* __restrict__ a2) {
    __shared__ float As[32][33];
    __shared__ __align__(16) float Ws[32][128];
    int t = threadIdx.x, lane = t & 31, wid = t >> 5;
    int r0 = blockIdx.x * 32;

    int gidx[4];
#pragma unroll
    for (int i = 0; i < 4; i++) gidx[i] = un[r0 + wid + 8 * i];

    float acc[4][4] = {};
    for (int kb = 0; kb < IN_DIM; kb += 32) {
#pragma unroll
        for (int i = 0; i < 4; i++)
            As[wid + 8 * i][lane] = gf[(size_t)gidx[i] * IN_DIM + kb + lane];
#pragma unroll
        for (int i = 0; i < 4; i++) {
            int y = wid + 8 * i;
            *(float4*)&Ws[y][4 * lane] =
                *(const float4*)&W[(kb + y) * OUT_DIM + 4 * lane];
        }
        __syncthreads();
#pragma unroll
        for (int kk = 0; kk < 32; kk++) {
            float4 wv = *(const float4*)&Ws[kk][4 * lane];
            float wvv[4] = {wv.x, wv.y, wv.z, wv.w};
            float av[4];
#pragma unroll
            for (int i = 0; i < 4; i++) av[i] = As[wid + 8 * i][kk];
#pragma unroll
            for (int i = 0; i < 4; i++)
#pragma unroll
                for (int c = 0; c < 4; c++) acc[i][c] += av[i] * wvv[c];
        }
        __syncthreads();
    }

    float4 a2v = *(const float4*)&a2[4 * lane];
#pragma unroll
    for (int i = 0; i < 4; i++) {
        int r = r0 + wid + 8 * i;
        float4 h = make_float4(acc[i][0], acc[i][1], acc[i][2], acc[i][3]);
        *(float4*)&g_hneigh[(size_t)r * OUT_DIM + 4 * lane] = h;
        float part = h.x * a2v.x + h.y * a2v.y + h.z * a2v.z + h.w * a2v.w;
#pragma unroll
        for (int o = 16; o; o >>= 1) part += __shfl_xor_sync(0xffffffffu, part, o);
        if (lane == 0) g_s2[r] = part;
    }
}

// ---------------- K2: S2max = max_n s2[n] (single block) ----------------
__global__ void k_s2max() {
    __shared__ float sm[8];
    int t = threadIdx.x;  // 256
    float m = -1e30f;
    for (int i = t; i < N_COLS; i += 256) m = fmaxf(m, g_s2[i]);
#pragma unroll
    for (int o = 16; o; o >>= 1) m = fmaxf(m, __shfl_xor_sync(0xffffffffu, m, o));
    if ((t & 31) == 0) sm[t >> 5] = m;
    __syncthreads();
    if (t < 32) {
        float v = (t < 8) ? sm[t] : -1e30f;
#pragma unroll
        for (int o = 4; o; o >>= 1) v = fmaxf(v, __shfl_xor_sync(0xffffffffu, v, o));
        if (t == 0) g_S2max = v;
    }
}

// ---------------- K3: p[n]=exp(s2-S2max), q[n]=exp(0.2(s2-S2max)) ----------
__global__ void k_pq() {
    int n = blockIdx.x * 256 + threadIdx.x;
    float d = g_s2[n] - g_S2max;
    g_p[n] = expf(d);
    g_q[n] = expf(ALPHA * d);
}

// ---------------- K4: per-row s1 -> t, P, Q ----------------
__global__ __launch_bounds__(256) void k_rowb(const float* __restrict__ gf,
                                              const int* __restrict__ nodes) {
    int t = threadIdx.x, lane = t & 31, wid = t >> 5;
    int b = blockIdx.x * 8 + wid;
    const float* row = gf + (size_t)nodes[b] * IN_DIM;
    float s = 0.f;
#pragma unroll
    for (int k = lane; k < IN_DIM; k += 32) s += row[k] * g_Wa1[k];
#pragma unroll
    for (int o = 16; o; o >>= 1) s += __shfl_xor_sync(0xffffffffu, s, o);
    if (lane == 0) {
        float v = s + g_S2max;                 // s1 + S2max
        float mh = (v >= 0.f) ? v : ALPHA * v; // safe shift m_hat >= row max
        g_t[b] = -s;
        g_P[b] = expf(v - mh);          // pos-branch row factor (<= 1)
        g_Q[b] = expf(ALPHA * v - mh);  // neg-branch row factor (<= 1)
    }
}

// ---------------- K5: fused masked-softmax-weighted sum + L2 normalize -----
// CTA: 256 threads, 32 b-rows x 128 features, sweep all 8192 n in tiles of 32.
// Thread (lane=tx, warp=wid): rows {wid, wid+8, wid+16, wid+24}, feats 4*tx..4*tx+3.
__global__ __launch_bounds__(256, 1) void k_main(const int* __restrict__ mask,
                                                 float* __restrict__ out) {
    __shared__ __align__(16) float Hs[32][128];          // 16 KB: h_neigh tile [n][f]
    __shared__ unsigned long long Ws2[32][32];           //  8 KB: dup-packed weights [b][n]

    int t = threadIdx.x, lane = t & 31, wid = t >> 5;
    int b0 = blockIdx.x * 32;

    float tB[4], PB[4], QB[4];
#pragma unroll
    for (int i = 0; i < 4; i++) {
        int b = b0 + wid + 8 * i;
        tB[i] = g_t[b]; PB[i] = g_P[b]; QB[i] = g_Q[b];
    }

    unsigned long long acc[4][2];
#pragma unroll
    for (int i = 0; i < 4; i++) { acc[i][0] = 0ull; acc[i][1] = 0ull; }

    // staging registers (global loads for NEXT tile overlap current FMA phase)
    float4 hreg[4];
    int mreg[4];
    float pv, qv, s2v;

    // prologue: load tile 0
    {
        int nb = 0;
#pragma unroll
        for (int k = 0; k < 4; k++) {
            int idx = t + 256 * k, row = idx >> 5, c4 = idx & 31;
            hreg[k] = *(const float4*)&g_hneigh[(size_t)(nb + row) * OUT_DIM + 4 * c4];
        }
#pragma unroll
        for (int i = 0; i < 4; i++)
            mreg[i] = mask[(size_t)(b0 + wid + 8 * i) * N_COLS + nb + lane];
        pv = g_p[nb + lane]; qv = g_q[nb + lane]; s2v = g_s2[nb + lane];
    }

    const int NT = N_COLS / 32;  // 256 tiles
    for (int it = 0; it < NT; ++it) {
        // --- store staged tile to smem ---
#pragma unroll
        for (int k = 0; k < 4; k++) {
            int idx = t + 256 * k, row = idx >> 5, c4 = idx & 31;
            *(float4*)&Hs[row][4 * c4] = hreg[k];
        }
#pragma unroll
        for (int i = 0; i < 4; i++) {
            float w = 0.f;
            if (mreg[i]) w = (s2v >= tB[i]) ? PB[i] * pv : QB[i] * qv;
            Ws2[wid + 8 * i][lane] = pk2(w, w);
        }
        __syncthreads();

        // --- prefetch next tile (global; latency hidden under FMA) ---
        if (it + 1 < NT) {
            int nb = (it + 1) * 32;
#pragma unroll
            for (int k = 0; k < 4; k++) {
                int idx = t + 256 * k, row = idx >> 5, c4 = idx & 31;
                hreg[k] = *(const float4*)&g_hneigh[(size_t)(nb + row) * OUT_DIM + 4 * c4];
            }
#pragma unroll
            for (int i = 0; i < 4; i++)
                mreg[i] = mask[(size_t)(b0 + wid + 8 * i) * N_COLS + nb + lane];
            pv = g_p[nb + lane]; qv = g_q[nb + lane]; s2v = g_s2[nb + lane];
        }

        // --- FMA phase: acc[b][f] += w[b][n] * h[n][f] (packed f32x2) ---
#pragma unroll
        for (int j = 0; j < 32; j++) {
            ulonglong2 hv = *(const ulonglong2*)&Hs[j][4 * lane];
#pragma unroll
            for (int i = 0; i < 4; i++) {
                unsigned long long w2 = Ws2[wid + 8 * i][j];
                acc[i][0] = fma2(w2, hv.x, acc[i][0]);
                acc[i][1] = fma2(w2, hv.y, acc[i][1]);
            }
        }
        __syncthreads();
    }

    // --- epilogue: L2 normalize per row (softmax denom cancels) ---
#pragma unroll
    for (int i = 0; i < 4; i++) {
        float h0, h1, h2, h3;
        upk2(acc[i][0], h0, h1);
        upk2(acc[i][1], h2, h3);
        float ss = h0 * h0 + h1 * h1 + h2 * h2 + h3 * h3;
#pragma unroll
        for (int o = 16; o; o >>= 1) ss += __shfl_xor_sync(0xffffffffu, ss, o);
        float scale = 1.f / fmaxf(sqrtf(ss), 1e-12f);
        float4 o4 = make_float4(h0 * scale, h1 * scale, h2 * scale, h3 * scale);
        *(float4*)&out[(size_t)(b0 + wid + 8 * i) * OUT_DIM + 4 * lane] = o4;
    }
}

// ---------------- launch ----------------
extern "C" void kernel_launch(void* const* d_in, const int* in_sizes, int n_in,
                              void* d_out, int out_size) {
    const float* gf    = (const float*)d_in[0];  // [100000, 256]
    const int*   nodes = (const int*)d_in[1];    // [4096]
    const int*   un    = (const int*)d_in[2];    // [8192]
    const int*   mask  = (const int*)d_in[3];    // [4096, 8192]
    const float* W     = (const float*)d_in[4];  // [256, 128]
    const float* a1    = (const float*)d_in[5];  // [128]
    const float* a2    = (const float*)d_in[6];  // [128]
    float* out = (float*)d_out;                  // [4096, 128]

    k_wa1<<<1, 256>>>(W, a1);
    k_hneigh<<<N_COLS / 32, 256>>>(gf, un, W, a2);
    k_s2max<<<1, 256>>>();
    k_pq<<<N_COLS / 256, 256>>>();
    k_rowb<<<B_ROWS / 8, 256>>>(gf, nodes);
    k_main<<<B_ROWS / 32, 256>>>(mask, out);
}

// round 5
// speedup vs baseline: 1.5622x; 1.5622x over previous
#include <cuda_runtime.h>
#include <cstdint>

typedef unsigned long long ull;

#define IN_DIM  256
#define OUT_DIM 128
#define B_ROWS  4096
#define N_COLS  8192
#define ALPHA   0.2f
#define NSPLIT  16
#define NCHUNK  (N_COLS / NSPLIT)   // 512
#define NTILES  (NCHUNK / 32)       // 16
#define WSTRIDE 130                 // ull per Ws2 row (64 pairs*2 + 2 pad)

// ---------------- device scratch (static, allocation-free) ----------------
__device__ __align__(16) float g_hneigh[N_COLS * OUT_DIM]; // chunk-permuted rows
__device__ float g_s2[N_COLS];
__device__ float g_p[N_COLS];
__device__ float g_q[N_COLS];
__device__ float g_t[B_ROWS];   // -s1[b]
__device__ float g_P[B_ROWS];
__device__ float g_Q[B_ROWS];
__device__ float g_Wa1[IN_DIM];
__device__ float g_S2max;
__device__ __align__(16) float g_part[(size_t)NSPLIT * B_ROWS * OUT_DIM]; // 33.5 MB

// ---------------- packed f32x2 + cp.async helpers ----------------
__device__ __forceinline__ ull fma2(ull a, ull b, ull c) {
    ull d;
    asm("fma.rn.f32x2 %0, %1, %2, %3;" : "=l"(d) : "l"(a), "l"(b), "l"(c));
    return d;
}
__device__ __forceinline__ ull pk2(float lo, float hi) {
    ull r;
    asm("mov.b64 %0, {%1, %2};" : "=l"(r) : "f"(lo), "f"(hi));
    return r;
}
__device__ __forceinline__ void cpa16(uint32_t s, const void* g) {
    asm volatile("cp.async.cg.shared.global [%0], [%1], 16;" :: "r"(s), "l"(g));
}

// ---------------- K0: Wa1[k] = sum_c W[k][c] * a1[c] ----------------
__global__ void k_wa1(const float* __restrict__ W, const float* __restrict__ a1) {
    int k = threadIdx.x;  // 256 threads
    const float* row = W + k * OUT_DIM;
    float s = 0.f;
#pragma unroll 8
    for (int c = 0; c < OUT_DIM; c++) s += row[c] * a1[c];
    g_Wa1[k] = s;
}

// ---------------- K1: h_neigh (chunk-permuted store) + s2 ----------------
// float4 chunk c stored at pos = (c&1)*16 + (c>>1): k_main's per-(fwarp,fgrp)
// pair of 16B loads then covers original floats [8u, 8u+8), conflict-free.
__global__ __launch_bounds__(256) void k_hneigh(
    const float* __restrict__ gf, const int* __restrict__ un,
    const float* __restrict__ W, const float* __restrict__ a2) {
    __shared__ float As[32][33];
    __shared__ __align__(16) float Ws[32][128];
    int t = threadIdx.x, lane = t & 31, wid = t >> 5;
    int r0 = blockIdx.x * 32;

    int gidx[4];
#pragma unroll
    for (int i = 0; i < 4; i++) gidx[i] = un[r0 + wid + 8 * i];

    float acc[4][4] = {};
    for (int kb = 0; kb < IN_DIM; kb += 32) {
#pragma unroll
        for (int i = 0; i < 4; i++)
            As[wid + 8 * i][lane] = gf[(size_t)gidx[i] * IN_DIM + kb + lane];
#pragma unroll
        for (int i = 0; i < 4; i++) {
            int y = wid + 8 * i;
            *(float4*)&Ws[y][4 * lane] =
                *(const float4*)&W[(kb + y) * OUT_DIM + 4 * lane];
        }
        __syncthreads();
#pragma unroll
        for (int kk = 0; kk < 32; kk++) {
            float4 wv = *(const float4*)&Ws[kk][4 * lane];
            float wvv[4] = {wv.x, wv.y, wv.z, wv.w};
            float av[4];
#pragma unroll
            for (int i = 0; i < 4; i++) av[i] = As[wid + 8 * i][kk];
#pragma unroll
            for (int i = 0; i < 4; i++)
#pragma unroll
                for (int c = 0; c < 4; c++) acc[i][c] += av[i] * wvv[c];
        }
        __syncthreads();
    }

    float4 a2v = *(const float4*)&a2[4 * lane];
    int pos = (lane & 1) * 16 + (lane >> 1);   // chunk permutation
#pragma unroll
    for (int i = 0; i < 4; i++) {
        int r = r0 + wid + 8 * i;
        float4 h = make_float4(acc[i][0], acc[i][1], acc[i][2], acc[i][3]);
        *(float4*)&g_hneigh[(size_t)r * OUT_DIM + 4 * pos] = h;
        float part = h.x * a2v.x + h.y * a2v.y + h.z * a2v.z + h.w * a2v.w;
#pragma unroll
        for (int o = 16; o; o >>= 1) part += __shfl_xor_sync(0xffffffffu, part, o);
        if (lane == 0) g_s2[r] = part;
    }
}

// ---------------- K2: S2max ----------------
__global__ void k_s2max() {
    __shared__ float sm[8];
    int t = threadIdx.x;  // 256
    float m = -1e30f;
    for (int i = t; i < N_COLS; i += 256) m = fmaxf(m, g_s2[i]);
#pragma unroll
    for (int o = 16; o; o >>= 1) m = fmaxf(m, __shfl_xor_sync(0xffffffffu, m, o));
    if ((t & 31) == 0) sm[t >> 5] = m;
    __syncthreads();
    if (t < 32) {
        float v = (t < 8) ? sm[t] : -1e30f;
#pragma unroll
        for (int o = 4; o; o >>= 1) v = fmaxf(v, __shfl_xor_sync(0xffffffffu, v, o));
        if (t == 0) g_S2max = v;
    }
}

// ---------------- K3: p, q ----------------
__global__ void k_pq() {
    int n = blockIdx.x * 256 + threadIdx.x;
    float d = g_s2[n] - g_S2max;
    g_p[n] = expf(d);
    g_q[n] = expf(ALPHA * d);
}

// ---------------- K4: per-row t, P, Q ----------------
__global__ __launch_bounds__(256) void k_rowb(const float* __restrict__ gf,
                                              const int* __restrict__ nodes) {
    int t = threadIdx.x, lane = t & 31, wid = t >> 5;
    int b = blockIdx.x * 8 + wid;
    const float* row = gf + (size_t)nodes[b] * IN_DIM;
    float s = 0.f;
#pragma unroll
    for (int k = lane; k < IN_DIM; k += 32) s += row[k] * g_Wa1[k];
#pragma unroll
    for (int o = 16; o; o >>= 1) s += __shfl_xor_sync(0xffffffffu, s, o);
    if (lane == 0) {
        float v = s + g_S2max;                 // s1 + S2max
        float mh = (v >= 0.f) ? v : ALPHA * v; // safe shift >= row max
        g_t[b] = -s;
        g_P[b] = expf(v - mh);
        g_Q[b] = expf(ALPHA * v - mh);
    }
}

// ---------------- K5: weighted sum, partials per n-split ----------------
// CTA: 256 thr (8 warps), output tile 128b x 128f, n-chunk 512 in tiles of 32.
// warp = (bwarp = wid>>1 -> 32b, fwarp = wid&1 -> 64f);
// lane = (bgrp = lane>>3 -> 8b, fgrp = lane&7 -> 8f); thread tile 8b x 8f.
//
// Weight table layout: pair pc=b>>1 stored at pos = swz(pc), where swz swaps
// bit-fields [3:2]<->[1:0] (involution, bits 5:4 kept). Load with
// woff[k]=2*(bwarp*16+4k+bgrp) then yields pc = bwarp*16+4*bgrp+k, i.e.
// acc[2k] <-> b = bwarp*32+bgrp*8+2k (matches epilogue), and the 4 bgrp lanes
// read 4 consecutive 16B blocks (conflict-free).
__global__ __launch_bounds__(256, 2) void k_main(const int* __restrict__ mask) {
    extern __shared__ __align__(16) char dsm[];
    ull* Hs0 = (ull*)dsm;              // 32 x 64 ull = 16 KB
    ull* Hs1 = Hs0 + 2048;             // 16 KB
    ull* Ws2 = Hs1 + 2048;             // 32 x 130 ull = 33.3 KB (dup-packed w)
    float* sT = (float*)(Ws2 + 32 * WSTRIDE);
    float* sP = sT + 128;
    float* sQ = sP + 128;

    const int tid = threadIdx.x, lane = tid & 31, wid = tid >> 5;
    const int bwarp = wid >> 1, fwarp = wid & 1;
    const int bgrp = lane >> 3, fgrp = lane & 7;
    const int gb0 = blockIdx.x * 128;
    const int nbase = blockIdx.y * NCHUNK;

    if (tid < 128) {
        sT[tid] = g_t[gb0 + tid];
        sP[tid] = g_P[gb0 + tid];
        sQ[tid] = g_Q[gb0 + tid];
    }

    const int hoff = 2 * (fwarp * 8 + fgrp);
    int woff[4];
#pragma unroll
    for (int k = 0; k < 4; k++) woff[k] = 2 * (bwarp * 16 + k * 4 + bgrp);

    // precomputed store slots: entry = swz(b>>1)*2 + (b&1)
    int wslot[16];
#pragma unroll
    for (int i = 0; i < 16; i++) {
        int b = wid * 16 + i;
        int pc = b >> 1;
        int pos = (pc & 48) | ((pc & 3) << 2) | ((pc & 12) >> 2);
        wslot[i] = pos * 2 + (b & 1);
    }

    const int* mbase = mask + (size_t)(gb0 + wid * 16) * N_COLS;

    // stage tile 0
    int mreg[16];
    float pv, qv, s2v;
    {
        int ng = nbase + lane;
#pragma unroll
        for (int i = 0; i < 16; i++) mreg[i] = mbase[(size_t)i * N_COLS + ng];
        pv = g_p[ng]; qv = g_q[ng]; s2v = g_s2[ng];
    }
    uint32_t hs_s0 = (uint32_t)__cvta_generic_to_shared(Hs0);
    uint32_t hs_s1 = (uint32_t)__cvta_generic_to_shared(Hs1);
    {
        const char* hsrc = (const char*)(g_hneigh + (size_t)nbase * OUT_DIM);
#pragma unroll
        for (int kk = 0; kk < 4; kk++)
            cpa16(hs_s0 + tid * 16 + kk * 4096, hsrc + tid * 16 + kk * 4096);
        asm volatile("cp.async.commit_group;");
    }

    ull acc[8][4];
#pragma unroll
    for (int i = 0; i < 8; i++)
#pragma unroll
        for (int k = 0; k < 4; k++) acc[i][k] = 0ull;

    __syncthreads();  // sT/sP/sQ visible

    for (int t = 0; t < NTILES; t++) {
        const int cur = t & 1;
        // prefetch h tile t+1 into other buffer
        if (t + 1 < NTILES) {
            const char* hsrc =
                (const char*)(g_hneigh + (size_t)(nbase + (t + 1) * 32) * OUT_DIM);
            uint32_t dst = (cur ? hs_s0 : hs_s1);
#pragma unroll
            for (int kk = 0; kk < 4; kk++)
                cpa16(dst + tid * 16 + kk * 4096, hsrc + tid * 16 + kk * 4096);
            asm volatile("cp.async.commit_group;");
        }
        // compute + store weights for tile t (warp handles 16 b rows, lane = n)
        ull* wrow = Ws2 + lane * WSTRIDE;
#pragma unroll
        for (int i = 0; i < 16; i++) {
            int b = wid * 16 + i;
            float w = 0.f;
            if (mreg[i]) w = (s2v >= sT[b]) ? sP[b] * pv : sQ[b] * qv;
            wrow[wslot[i]] = pk2(w, w);
        }
        // stage tile t+1 scalars/mask
        if (t + 1 < NTILES) {
            int ng = nbase + (t + 1) * 32 + lane;
#pragma unroll
            for (int i = 0; i < 16; i++) mreg[i] = mbase[(size_t)i * N_COLS + ng];
            pv = g_p[ng]; qv = g_q[ng]; s2v = g_s2[ng];
            asm volatile("cp.async.wait_group 1;");
        } else {
            asm volatile("cp.async.wait_group 0;");
        }
        __syncthreads();  // Hs[t] + Ws2 ready

        const ull* H = cur ? Hs1 : Hs0;
#pragma unroll 4
        for (int j = 0; j < 32; j++) {
            const ull* hr = H + j * 64 + hoff;
            ulonglong2 h0 = *(const ulonglong2*)hr;
            ulonglong2 h1 = *(const ulonglong2*)(hr + 32);
            const ull* wr = Ws2 + j * WSTRIDE;
#pragma unroll
            for (int k = 0; k < 4; k++) {
                ulonglong2 w2 = *(const ulonglong2*)(wr + woff[k]);
                acc[2 * k][0] = fma2(w2.x, h0.x, acc[2 * k][0]);
                acc[2 * k][1] = fma2(w2.x, h0.y, acc[2 * k][1]);
                acc[2 * k][2] = fma2(w2.x, h1.x, acc[2 * k][2]);
                acc[2 * k][3] = fma2(w2.x, h1.y, acc[2 * k][3]);
                acc[2 * k + 1][0] = fma2(w2.y, h0.x, acc[2 * k + 1][0]);
                acc[2 * k + 1][1] = fma2(w2.y, h0.y, acc[2 * k + 1][1]);
                acc[2 * k + 1][2] = fma2(w2.y, h1.x, acc[2 * k + 1][2]);
                acc[2 * k + 1][3] = fma2(w2.y, h1.y, acc[2 * k + 1][3]);
            }
        }
        __syncthreads();  // FMA done before Ws2 rewritten
    }

    // epilogue: write partials (acc[i] <-> row brow0+i, feats f0..f0+7)
    const int brow0 = gb0 + bwarp * 32 + bgrp * 8;
    const int f0 = fwarp * 64 + fgrp * 8;
    float* pbase = g_part + (size_t)blockIdx.y * B_ROWS * OUT_DIM;
#pragma unroll
    for (int i = 0; i < 8; i++) {
        ull* dst = (ull*)(pbase + (size_t)(brow0 + i) * OUT_DIM + f0);
        *(ulonglong2*)dst = make_ulonglong2(acc[i][0], acc[i][1]);
        *(ulonglong2*)(dst + 2) = make_ulonglong2(acc[i][2], acc[i][3]);
    }
}

// ---------------- K6: reduce partials + L2 normalize ----------------
__global__ __launch_bounds__(128) void k_finish(float* __restrict__ out) {
    __shared__ float red[4];
    int b = blockIdx.x, f = threadIdx.x;
    float s = 0.f;
#pragma unroll
    for (int k = 0; k < NSPLIT; k++)
        s += g_part[((size_t)k * B_ROWS + b) * OUT_DIM + f];
    float ss = s * s;
#pragma unroll
    for (int o = 16; o; o >>= 1) ss += __shfl_xor_sync(0xffffffffu, ss, o);
    if ((f & 31) == 0) red[f >> 5] = ss;
    __syncthreads();
    float tot = red[0] + red[1] + red[2] + red[3];
    out[b * OUT_DIM + f] = s / fmaxf(sqrtf(tot), 1e-12f);
}

// ---------------- launch ----------------
extern "C" void kernel_launch(void* const* d_in, const int* in_sizes, int n_in,
                              void* d_out, int out_size) {
    const float* gf    = (const float*)d_in[0];  // [100000, 256]
    const int*   nodes = (const int*)d_in[1];    // [4096]
    const int*   un    = (const int*)d_in[2];    // [8192]
    const int*   mask  = (const int*)d_in[3];    // [4096, 8192]
    const float* W     = (const float*)d_in[4];  // [256, 128]
    const float* a1    = (const float*)d_in[5];  // [128]
    const float* a2    = (const float*)d_in[6];  // [128]
    float* out = (float*)d_out;                  // [4096, 128]

    static int smem_set = 0;
    const int SMEM = (2048 * 2 + 32 * WSTRIDE) * 8 + 3 * 128 * 4;  // 67584
    if (!smem_set) {
        cudaFuncSetAttribute(k_main, cudaFuncAttributeMaxDynamicSharedMemorySize, SMEM);
        smem_set = 1;
    }

    k_wa1<<<1, 256>>>(W, a1);
    k_hneigh<<<N_COLS / 32, 256>>>(gf, un, W, a2);
    k_s2max<<<1, 256>>>();
    k_pq<<<N_COLS / 256, 256>>>();
    k_rowb<<<B_ROWS / 8, 256>>>(gf, nodes);
    k_main<<<dim3(B_ROWS / 128, NSPLIT), 256, SMEM>>>(mask);
    k_finish<<<B_ROWS, 128>>>(out);
}

// round 7
// speedup vs baseline: 2.9459x; 1.8857x over previous
#include <cuda_runtime.h>
#include <cstdint>

typedef unsigned long long ull;

#define IN_DIM  256
#define OUT_DIM 128
#define B_ROWS  4096
#define N_COLS  8192
#define ALPHA   0.2f
#define NSPLIT  8
#define NCHUNK  (N_COLS / NSPLIT)   // 1024 n per CTA
#define KT      32                  // n per smem tile
#define NT      (NCHUNK / KT)       // 32 tiles
#define RSTRIDE 36                  // floats per smem tile row (bank-bijective)

// ---------------- device scratch (static, allocation-free) ----------------
__device__ __align__(16) float g_hbT[OUT_DIM * N_COLS]; // [128 f][8192 n], tf32-rounded
__device__ float g_s2[N_COLS];
__device__ float g_p[N_COLS];
__device__ float g_q[N_COLS];
__device__ float g_t[B_ROWS];   // -s1[b]
__device__ float g_P[B_ROWS];
__device__ float g_Q[B_ROWS];
__device__ float g_Wa1[IN_DIM];
__device__ float g_S2max;
__device__ __align__(16) float g_part[(size_t)NSPLIT * B_ROWS * OUT_DIM]; // 16 MB

// ---------------- helpers ----------------
__device__ __forceinline__ uint32_t smem_u32(const void* p) {
    uint32_t a;
    asm("{ .reg .u64 t; cvta.to.shared.u64 t, %1; cvt.u32.u64 %0, t; }"
        : "=r"(a) : "l"(p));
    return a;
}
__device__ __forceinline__ void cpa16(uint32_t s, const void* g) {
    asm volatile("cp.async.cg.shared.global [%0], [%1], 16;" :: "r"(s), "l"(g));
}
__device__ __forceinline__ uint32_t f2tf32(float f) {
    uint32_t u;
    asm("cvt.rna.tf32.f32 %0, %1;" : "=r"(u) : "f"(f));
    return u;
}
__device__ __forceinline__ uint32_t lds32(uint32_t a) {
    uint32_t v;
    asm volatile("ld.shared.b32 %0, [%1];" : "=r"(v) : "r"(a));
    return v;
}
__device__ __forceinline__ void sts32(uint32_t a, uint32_t v) {
    asm volatile("st.shared.b32 [%0], %1;" :: "r"(a), "r"(v));
}
__device__ __forceinline__ void mma_tf32(float* d, const uint32_t* a,
                                         uint32_t b0, uint32_t b1) {
    asm volatile(
        "mma.sync.aligned.m16n8k8.row.col.f32.tf32.tf32.f32 "
        "{%0,%1,%2,%3},{%4,%5,%6,%7},{%8,%9},{%0,%1,%2,%3};"
        : "+f"(d[0]), "+f"(d[1]), "+f"(d[2]), "+f"(d[3])
        : "r"(a[0]), "r"(a[1]), "r"(a[2]), "r"(a[3]), "r"(b0), "r"(b1));
}

// ---------------- K0: Wa1[k] = sum_c W[k][c] * a1[c] ----------------
__global__ void k_wa1(const float* __restrict__ W, const float* __restrict__ a1) {
    int k = threadIdx.x;  // 256 threads
    const float* row = W + k * OUT_DIM;
    float s = 0.f;
#pragma unroll 8
    for (int c = 0; c < OUT_DIM; c++) s += row[c] * a1[c];
    g_Wa1[k] = s;
}

// ---------------- K1: h = gf[un] @ W -> transposed tf32 g_hbT; s2 ----------
__global__ __launch_bounds__(256) void k_hneigh(
    const float* __restrict__ gf, const int* __restrict__ un,
    const float* __restrict__ W, const float* __restrict__ a2) {
    __shared__ float As[32][33];
    __shared__ __align__(16) float Ws[32][132];  // W tile; reused for transpose
    int t = threadIdx.x, lane = t & 31, wid = t >> 5;
    int r0 = blockIdx.x * 32;

    int gidx[4];
#pragma unroll
    for (int i = 0; i < 4; i++) gidx[i] = un[r0 + wid + 8 * i];

    float acc[4][4] = {};
    for (int kb = 0; kb < IN_DIM; kb += 32) {
#pragma unroll
        for (int i = 0; i < 4; i++)
            As[wid + 8 * i][lane] = gf[(size_t)gidx[i] * IN_DIM + kb + lane];
#pragma unroll
        for (int i = 0; i < 4; i++) {
            int y = wid + 8 * i;
            *(float4*)&Ws[y][4 * lane] =
                *(const float4*)&W[(kb + y) * OUT_DIM + 4 * lane];
        }
        __syncthreads();
#pragma unroll
        for (int kk = 0; kk < 32; kk++) {
            float4 wv = *(const float4*)&Ws[kk][4 * lane];
            float wvv[4] = {wv.x, wv.y, wv.z, wv.w};
            float av[4];
#pragma unroll
            for (int i = 0; i < 4; i++) av[i] = As[wid + 8 * i][kk];
#pragma unroll
            for (int i = 0; i < 4; i++)
#pragma unroll
                for (int c = 0; c < 4; c++) acc[i][c] += av[i] * wvv[c];
        }
        __syncthreads();
    }

    // s2[r] = h[r] . a2 (full fp32)
    float4 a2v = *(const float4*)&a2[4 * lane];
#pragma unroll
    for (int i = 0; i < 4; i++) {
        int r = r0 + wid + 8 * i;
        float part = acc[i][0] * a2v.x + acc[i][1] * a2v.y +
                     acc[i][2] * a2v.z + acc[i][3] * a2v.w;
#pragma unroll
        for (int o = 16; o; o >>= 1) part += __shfl_xor_sync(0xffffffffu, part, o);
        if (lane == 0) g_s2[r] = part;
    }

    // transpose via smem -> g_hbT[f][n], tf32-rounded
#pragma unroll
    for (int i = 0; i < 4; i++)
        *(float4*)&Ws[wid + 8 * i][4 * lane] =
            make_float4(acc[i][0], acc[i][1], acc[i][2], acc[i][3]);
    __syncthreads();
    {
        int f = t >> 1, half = t & 1;
        float v[16];
#pragma unroll
        for (int j = 0; j < 16; j++)
            v[j] = __uint_as_float(f2tf32(Ws[half * 16 + j][f]));
        float* dst = g_hbT + (size_t)f * N_COLS + r0 + half * 16;
#pragma unroll
        for (int k = 0; k < 4; k++)
            *(float4*)&dst[4 * k] = make_float4(v[4 * k], v[4 * k + 1],
                                                v[4 * k + 2], v[4 * k + 3]);
    }
}

// ---------------- K2: S2max + p/q (fused, single block) ----------------
__global__ __launch_bounds__(1024) void k_sm() {
    __shared__ float sm[32];
    __shared__ float sM;
    int t = threadIdx.x;
    float m = -1e30f;
    for (int i = t; i < N_COLS; i += 1024) m = fmaxf(m, g_s2[i]);
#pragma unroll
    for (int o = 16; o; o >>= 1) m = fmaxf(m, __shfl_xor_sync(0xffffffffu, m, o));
    if ((t & 31) == 0) sm[t >> 5] = m;
    __syncthreads();
    if (t < 32) {
        float v = sm[t];
#pragma unroll
        for (int o = 16; o; o >>= 1) v = fmaxf(v, __shfl_xor_sync(0xffffffffu, v, o));
        if (t == 0) { sM = v; g_S2max = v; }
    }
    __syncthreads();
    float M = sM;
    for (int i = t; i < N_COLS; i += 1024) {
        float d = g_s2[i] - M;
        g_p[i] = expf(d);
        g_q[i] = expf(ALPHA * d);
    }
}

// ---------------- K3: per-row t, P, Q ----------------
__global__ __launch_bounds__(256) void k_rowb(const float* __restrict__ gf,
                                              const int* __restrict__ nodes) {
    int t = threadIdx.x, lane = t & 31, wid = t >> 5;
    int b = blockIdx.x * 8 + wid;
    const float* row = gf + (size_t)nodes[b] * IN_DIM;
    float s = 0.f;
#pragma unroll
    for (int k = lane; k < IN_DIM; k += 32) s += row[k] * g_Wa1[k];
#pragma unroll
    for (int o = 16; o; o >>= 1) s += __shfl_xor_sync(0xffffffffu, s, o);
    if (lane == 0) {
        float v = s + g_S2max;                 // s1 + S2max
        float mh = (v >= 0.f) ? v : ALPHA * v; // safe shift >= row max
        g_t[b] = -s;
        g_P[b] = expf(v - mh);
        g_Q[b] = expf(ALPHA * v - mh);
    }
}

// ---------------- K4: mma.sync tf32 weighted sum -> partials ----------------
// CTA 256 thr (8 warps), output 128b x 128f, n-chunk 1024 in 32 K-tiles of 32.
// Warp grid 4(b) x 2(f): warp tile 32b x 64f; HMMA m16n8k8 tf32.
// Smem tiles use RSTRIDE=36 floats/row: LDS bank = (4*(lane>>2)+(lane&3)) -> CF.
__global__ __launch_bounds__(256, 2) void k_main(const int* __restrict__ mask) {
    extern __shared__ __align__(16) char dsm[];
    const uint32_t sb = smem_u32(dsm);
    const uint32_t Wt[2] = {sb, sb + 18432};           // 128*36*4 each
    const uint32_t Ht[2] = {sb + 36864, sb + 55296};
    float* sT = (float*)(dsm + 73728);
    float* sP = sT + 128;
    float* sQ = sP + 128;

    const int tid = threadIdx.x, lane = tid & 31, wid = tid >> 5;
    const int qr = lane >> 2, qc = lane & 3;
    const int bwarp = wid >> 1, fwarp = wid & 1;
    const int gb0 = blockIdx.x * 128;
    const int nbase = blockIdx.y * NCHUNK;

    if (tid < 128) {
        sT[tid] = g_t[gb0 + tid];
        sP[tid] = g_P[gb0 + tid];
        sQ[tid] = g_Q[gb0 + tid];
    }

    // --- w-gen mapping: warp covers b-local [wid*16, wid*16+16), lane = n ---
    const int* mbase = mask + (size_t)(gb0 + wid * 16) * N_COLS + nbase + lane;
    const uint32_t wgbase = wid * 16 * (RSTRIDE * 4) + lane * 4;

    // --- B cp.async mapping: f = tid>>1, two 64B halves ---
    const int bf_row = tid >> 1, bf_half = tid & 1;
    const uint32_t hstore = (uint32_t)bf_row * (RSTRIDE * 4) + bf_half * 64;
    const float* bsrc = g_hbT + (size_t)bf_row * N_COLS + nbase + bf_half * 16;

    // stage tile 0
    int mreg[16];
    float pv, qv, s2v;
#pragma unroll
    for (int i = 0; i < 16; i++) mreg[i] = mbase[(size_t)i * N_COLS];
    { int n = nbase + lane; pv = g_p[n]; qv = g_q[n]; s2v = g_s2[n]; }
#pragma unroll
    for (int k = 0; k < 4; k++) cpa16(Ht[0] + hstore + k * 16, bsrc + 4 * k);
    asm volatile("cp.async.commit_group;");

    float d[2][8][4];
#pragma unroll
    for (int mb = 0; mb < 2; mb++)
#pragma unroll
        for (int fb = 0; fb < 8; fb++)
#pragma unroll
            for (int c = 0; c < 4; c++) d[mb][fb][c] = 0.f;

    __syncthreads();  // sT/sP/sQ visible

    const uint32_t wmma0 = bwarp * 32 * (RSTRIDE * 4) + qr * (RSTRIDE * 4) + qc * 4;
    const uint32_t hmma0 = fwarp * 64 * (RSTRIDE * 4) + qr * (RSTRIDE * 4) + qc * 4;

    for (int t = 0; t < NT; t++) {
        const int cur = t & 1;
        // generate w tile t (tf32) into Wt[cur]
        {
            uint32_t wa = Wt[cur] + wgbase;
#pragma unroll
            for (int i = 0; i < 16; i++) {
                int b = wid * 16 + i;
                float w = 0.f;
                if (mreg[i]) w = (s2v >= sT[b]) ? sP[b] * pv : sQ[b] * qv;
                sts32(wa, f2tf32(w));
                wa += RSTRIDE * 4;
            }
        }
        // stage tile t+1 (mask + n-scalars)
        if (t + 1 < NT) {
            const int* mb2 = mbase + (t + 1) * KT;
#pragma unroll
            for (int i = 0; i < 16; i++) mreg[i] = mb2[(size_t)i * N_COLS];
            int n = nbase + (t + 1) * KT + lane;
            pv = g_p[n]; qv = g_q[n]; s2v = g_s2[n];
        }
        asm volatile("cp.async.wait_group 0;");
        __syncthreads();  // Wt[cur] + Ht[cur] ready for all warps

        // issue cp.async for t+1 (buffer safe: all warps done MMA(t-1))
        if (t + 1 < NT) {
            const float* src = bsrc + (t + 1) * KT;
#pragma unroll
            for (int k = 0; k < 4; k++)
                cpa16(Ht[cur ^ 1] + hstore + k * 16, src + 4 * k);
            asm volatile("cp.async.commit_group;");
        }

        // MMA phase: 2 mb x 8 fb x 4 j = 64 HMMA
        const uint32_t wbase = Wt[cur] + wmma0;
        const uint32_t hbase = Ht[cur] + hmma0;
#pragma unroll
        for (int j = 0; j < 4; j++) {
            uint32_t a[2][4];
#pragma unroll
            for (int mb = 0; mb < 2; mb++) {
                uint32_t a0 = wbase + mb * 16 * (RSTRIDE * 4) + j * 32;
                a[mb][0] = lds32(a0);
                a[mb][1] = lds32(a0 + 8 * (RSTRIDE * 4));
                a[mb][2] = lds32(a0 + 16);
                a[mb][3] = lds32(a0 + 8 * (RSTRIDE * 4) + 16);
            }
#pragma unroll
            for (int fb = 0; fb < 8; fb++) {
                uint32_t h0 = hbase + fb * 8 * (RSTRIDE * 4) + j * 32;
                uint32_t b0 = lds32(h0);
                uint32_t b1 = lds32(h0 + 16);
                mma_tf32(d[0][fb], a[0], b0, b1);
                mma_tf32(d[1][fb], a[1], b0, b1);
            }
        }
        __syncthreads();  // MMA(t) done before Wt[cur^1] regen / Ht reuse
    }

    // epilogue: write partials
    float* pbase = g_part + (size_t)blockIdx.y * B_ROWS * OUT_DIM;
#pragma unroll
    for (int mb = 0; mb < 2; mb++) {
        int brow = gb0 + bwarp * 32 + mb * 16 + qr;
#pragma unroll
        for (int fb = 0; fb < 8; fb++) {
            int f = fwarp * 64 + fb * 8 + qc * 2;
            float* p0 = pbase + (size_t)brow * OUT_DIM + f;
            *(float2*)p0 = make_float2(d[mb][fb][0], d[mb][fb][1]);
            *(float2*)(p0 + 8 * OUT_DIM) = make_float2(d[mb][fb][2], d[mb][fb][3]);
        }
    }
}

// ---------------- K5: reduce partials + L2 normalize ----------------
__global__ __launch_bounds__(128) void k_finish(float* __restrict__ out) {
    __shared__ float red[4];
    int b = blockIdx.x, f = threadIdx.x;
    float s = 0.f;
#pragma unroll
    for (int k = 0; k < NSPLIT; k++)
        s += g_part[((size_t)k * B_ROWS + b) * OUT_DIM + f];
    float ss = s * s;
#pragma unroll
    for (int o = 16; o; o >>= 1) ss += __shfl_xor_sync(0xffffffffu, ss, o);
    if ((f & 31) == 0) red[f >> 5] = ss;
    __syncthreads();
    float tot = red[0] + red[1] + red[2] + red[3];
    out[b * OUT_DIM + f] = s / fmaxf(sqrtf(tot), 1e-12f);
}

// ---------------- launch ----------------
extern "C" void kernel_launch(void* const* d_in, const int* in_sizes, int n_in,
                              void* d_out, int out_size) {
    const float* gf    = (const float*)d_in[0];  // [100000, 256]
    const int*   nodes = (const int*)d_in[1];    // [4096]
    const int*   un    = (const int*)d_in[2];    // [8192]
    const int*   mask  = (const int*)d_in[3];    // [4096, 8192]
    const float* W     = (const float*)d_in[4];  // [256, 128]
    const float* a1    = (const float*)d_in[5];  // [128]
    const float* a2    = (const float*)d_in[6];  // [128]
    float* out = (float*)d_out;                  // [4096, 128]

    static int smem_set = 0;
    const int SMEM = 73728 + 3 * 128 * 4;  // 2x Wt + 2x Ht + sT/sP/sQ = 75264
    if (!smem_set) {
        cudaFuncSetAttribute(k_main, cudaFuncAttributeMaxDynamicSharedMemorySize, SMEM);
        smem_set = 1;
    }

    k_wa1<<<1, 256>>>(W, a1);
    k_hneigh<<<N_COLS / 32, 256>>>(gf, un, W, a2);
    k_sm<<<1, 1024>>>();
    k_rowb<<<B_ROWS / 8, 256>>>(gf, nodes);
    k_main<<<dim3(B_ROWS / 128, NSPLIT), 256, SMEM>>>(mask);
    k_finish<<<B_ROWS, 128>>>(out);
}

// round 8
// speedup vs baseline: 3.5036x; 1.1893x over previous
#include <cuda_runtime.h>
#include <cuda_fp16.h>
#include <cstdint>

typedef unsigned long long ull;

#define IN_DIM  256
#define OUT_DIM 128
#define B_ROWS  4096
#define N_COLS  8192
#define ALPHA   0.2f
#define NSPLIT  8
#define NCHUNK  (N_COLS / NSPLIT)   // 1024 n per CTA
#define KT      32                  // n per smem K-tile
#define NT      (NCHUNK / KT)       // 32 tiles
#define ST      80                  // bytes per smem tile row (40 halves; CF banks)

// ---------------- device scratch (static, allocation-free) ----------------
__device__ __align__(16) __half g_hbT[OUT_DIM * N_COLS]; // [128 f][8192 n] fp16
__device__ float g_s2[N_COLS];
__device__ float g_p[N_COLS];
__device__ float g_q[N_COLS];
__device__ float g_t[B_ROWS];   // -s1[b]
__device__ float g_P[B_ROWS];
__device__ float g_Q[B_ROWS];
__device__ float g_Wa1[IN_DIM];
__device__ float g_S2max;
__device__ __align__(16) float g_part[(size_t)NSPLIT * B_ROWS * OUT_DIM]; // 16 MB

// ---------------- helpers ----------------
__device__ __forceinline__ uint32_t smem_u32(const void* p) {
    uint32_t a;
    asm("{ .reg .u64 t; cvta.to.shared.u64 t, %1; cvt.u32.u64 %0, t; }"
        : "=r"(a) : "l"(p));
    return a;
}
__device__ __forceinline__ void cpa16(uint32_t s, const void* g) {
    asm volatile("cp.async.cg.shared.global [%0], [%1], 16;" :: "r"(s), "l"(g));
}
__device__ __forceinline__ uint32_t lds32(uint32_t a) {
    uint32_t v;
    asm volatile("ld.shared.b32 %0, [%1];" : "=r"(v) : "r"(a));
    return v;
}
__device__ __forceinline__ void sts16(uint32_t a, unsigned short v) {
    asm volatile("st.shared.b16 [%0], %1;" :: "r"(a), "h"(v));
}
__device__ __forceinline__ void mma_f16(float* d, const uint32_t* a,
                                        uint32_t b0, uint32_t b1) {
    asm volatile(
        "mma.sync.aligned.m16n8k16.row.col.f32.f16.f16.f32 "
        "{%0,%1,%2,%3},{%4,%5,%6,%7},{%8,%9},{%0,%1,%2,%3};"
        : "+f"(d[0]), "+f"(d[1]), "+f"(d[2]), "+f"(d[3])
        : "r"(a[0]), "r"(a[1]), "r"(a[2]), "r"(a[3]), "r"(b0), "r"(b1));
}

// ---------------- K0: Wa1[k] = sum_c W[k][c] * a1[c] ----------------
__global__ void k_wa1(const float* __restrict__ W, const float* __restrict__ a1) {
    int k = threadIdx.x;  // 256 threads
    const float* row = W + k * OUT_DIM;
    float s = 0.f;
#pragma unroll 8
    for (int c = 0; c < OUT_DIM; c++) s += row[c] * a1[c];
    g_Wa1[k] = s;
}

// ---------------- K1: h = gf[un] @ W -> fp16 hT; s2 (fp32) ----------------
__global__ __launch_bounds__(256) void k_hneigh(
    const float* __restrict__ gf, const int* __restrict__ un,
    const float* __restrict__ W, const float* __restrict__ a2) {
    __shared__ float As[32][33];
    __shared__ __align__(16) float Ws[32][132];  // W tile; reused for transpose
    int t = threadIdx.x, lane = t & 31, wid = t >> 5;
    int r0 = blockIdx.x * 32;

    int gidx[4];
#pragma unroll
    for (int i = 0; i < 4; i++) gidx[i] = un[r0 + wid + 8 * i];

    float acc[4][4] = {};
    for (int kb = 0; kb < IN_DIM; kb += 32) {
#pragma unroll
        for (int i = 0; i < 4; i++)
            As[wid + 8 * i][lane] = gf[(size_t)gidx[i] * IN_DIM + kb + lane];
#pragma unroll
        for (int i = 0; i < 4; i++) {
            int y = wid + 8 * i;
            *(float4*)&Ws[y][4 * lane] =
                *(const float4*)&W[(kb + y) * OUT_DIM + 4 * lane];
        }
        __syncthreads();
#pragma unroll
        for (int kk = 0; kk < 32; kk++) {
            float4 wv = *(const float4*)&Ws[kk][4 * lane];
            float wvv[4] = {wv.x, wv.y, wv.z, wv.w};
            float av[4];
#pragma unroll
            for (int i = 0; i < 4; i++) av[i] = As[wid + 8 * i][kk];
#pragma unroll
            for (int i = 0; i < 4; i++)
#pragma unroll
                for (int c = 0; c < 4; c++) acc[i][c] += av[i] * wvv[c];
        }
        __syncthreads();
    }

    // s2[r] = h[r] . a2 (full fp32)
    float4 a2v = *(const float4*)&a2[4 * lane];
#pragma unroll
    for (int i = 0; i < 4; i++) {
        int r = r0 + wid + 8 * i;
        float part = acc[i][0] * a2v.x + acc[i][1] * a2v.y +
                     acc[i][2] * a2v.z + acc[i][3] * a2v.w;
#pragma unroll
        for (int o = 16; o; o >>= 1) part += __shfl_xor_sync(0xffffffffu, part, o);
        if (lane == 0) g_s2[r] = part;
    }

    // transpose via smem -> g_hbT[f][n] in fp16
#pragma unroll
    for (int i = 0; i < 4; i++)
        *(float4*)&Ws[wid + 8 * i][4 * lane] =
            make_float4(acc[i][0], acc[i][1], acc[i][2], acc[i][3]);
    __syncthreads();
    {
        int f = t >> 1, half = t & 1;
        __half2 v2[8];
#pragma unroll
        for (int j = 0; j < 8; j++)
            v2[j] = __floats2half2_rn(Ws[half * 16 + 2 * j][f],
                                      Ws[half * 16 + 2 * j + 1][f]);
        __half* dst = g_hbT + (size_t)f * N_COLS + r0 + half * 16;
        *(uint4*)dst = *(uint4*)&v2[0];
        *(uint4*)(dst + 8) = *(uint4*)&v2[4];
    }
}

// ---------------- K2: S2max + p/q (fused, single block) ----------------
__global__ __launch_bounds__(1024) void k_sm() {
    __shared__ float sm[32];
    __shared__ float sM;
    int t = threadIdx.x;
    float m = -1e30f;
    for (int i = t; i < N_COLS; i += 1024) m = fmaxf(m, g_s2[i]);
#pragma unroll
    for (int o = 16; o; o >>= 1) m = fmaxf(m, __shfl_xor_sync(0xffffffffu, m, o));
    if ((t & 31) == 0) sm[t >> 5] = m;
    __syncthreads();
    if (t < 32) {
        float v = sm[t];
#pragma unroll
        for (int o = 16; o; o >>= 1) v = fmaxf(v, __shfl_xor_sync(0xffffffffu, v, o));
        if (t == 0) { sM = v; g_S2max = v; }
    }
    __syncthreads();
    float M = sM;
    for (int i = t; i < N_COLS; i += 1024) {
        float d = g_s2[i] - M;
        g_p[i] = expf(d);
        g_q[i] = expf(ALPHA * d);
    }
}

// ---------------- K3: per-row t, P, Q ----------------
__global__ __launch_bounds__(256) void k_rowb(const float* __restrict__ gf,
                                              const int* __restrict__ nodes) {
    int t = threadIdx.x, lane = t & 31, wid = t >> 5;
    int b = blockIdx.x * 8 + wid;
    const float* row = gf + (size_t)nodes[b] * IN_DIM;
    float s = 0.f;
#pragma unroll
    for (int k = lane; k < IN_DIM; k += 32) s += row[k] * g_Wa1[k];
#pragma unroll
    for (int o = 16; o; o >>= 1) s += __shfl_xor_sync(0xffffffffu, s, o);
    if (lane == 0) {
        float v = s + g_S2max;                 // s1 + S2max
        float mh = (v >= 0.f) ? v : ALPHA * v; // safe shift >= row max
        g_t[b] = -s;
        g_P[b] = expf(v - mh);
        g_Q[b] = expf(ALPHA * v - mh);
    }
}

// ---------------- K4: mma.sync fp16 weighted sum -> partials ----------------
// CTA 256 thr (8 warps), output 128b x 128f, n-chunk 1024 in 32 K-tiles of 32.
// Warp grid 4(b) x 2(f): warp tile 32b x 64f; HMMA m16n8k16 f16 (fp32 acc).
// Smem rows ST=80B: A/B frag LDS bank = (20*qr + qc) -> conflict-free.
// Single __syncthreads per tile (both operands double-buffered);
// h-tiles triple-buffered, cp.async depth 2 (wait_group 1).
__global__ __launch_bounds__(256, 2) void k_main(const int* __restrict__ mask) {
    extern __shared__ __align__(16) char dsm[];
    const uint32_t sb = smem_u32(dsm);
    const uint32_t Wt[2] = {sb, sb + 10240};                    // 128*80 each
    const uint32_t Ht[3] = {sb + 20480, sb + 30720, sb + 40960};
    float* sT = (float*)(dsm + 51200);
    float* sP = sT + 128;
    float* sQ = sP + 128;

    const int tid = threadIdx.x, lane = tid & 31, wid = tid >> 5;
    const int qr = lane >> 2, qc = lane & 3;
    const int bwarp = wid >> 1, fwarp = wid & 1;
    const int gb0 = blockIdx.x * 128;
    const int nbase = blockIdx.y * NCHUNK;

    if (tid < 128) {
        sT[tid] = g_t[gb0 + tid];
        sP[tid] = g_P[gb0 + tid];
        sQ[tid] = g_Q[gb0 + tid];
    }

    // --- w-gen mapping: warp covers b-local [wid*16, wid*16+16), lane = n ---
    const int* mbase = mask + (size_t)(gb0 + wid * 16) * N_COLS + nbase + lane;
    const uint32_t wgbase = (uint32_t)(wid * 16) * ST + lane * 2;

    // --- h cp.async mapping: f = tid>>1, two 16B chunks of the 64B row ---
    const int hf = tid >> 1, hc = tid & 1;
    const uint32_t hstore = (uint32_t)hf * ST + hc * 32;
    const __half* hsrc = g_hbT + (size_t)hf * N_COLS + nbase + hc * 16;

    // stage tile 0 (mask + n-scalars), prefetch h tiles 0 and 1
    int mreg[16];
    float pv, qv, s2v;
#pragma unroll
    for (int i = 0; i < 16; i++) mreg[i] = mbase[(size_t)i * N_COLS];
    { int n = nbase + lane; pv = g_p[n]; qv = g_q[n]; s2v = g_s2[n]; }
    cpa16(Ht[0] + hstore, hsrc);
    cpa16(Ht[0] + hstore + 16, hsrc + 8);
    asm volatile("cp.async.commit_group;");
    cpa16(Ht[1] + hstore, hsrc + KT);
    cpa16(Ht[1] + hstore + 16, hsrc + KT + 8);
    asm volatile("cp.async.commit_group;");

    float d[2][8][4];
#pragma unroll
    for (int mb = 0; mb < 2; mb++)
#pragma unroll
        for (int fb = 0; fb < 8; fb++)
#pragma unroll
            for (int c = 0; c < 4; c++) d[mb][fb][c] = 0.f;

    __syncthreads();  // sT/sP/sQ visible

    const uint32_t wmma0 = (uint32_t)(bwarp * 32) * ST + qr * ST + qc * 4;
    const uint32_t hmma0 = (uint32_t)(fwarp * 64) * ST + qr * ST + qc * 4;

    int hbi = 0;  // h buffer index for tile t
    for (int t = 0; t < NT; t++) {
        const int wcur = t & 1;
        // generate w tile t (fp16) into Wt[wcur]
        {
            uint32_t wa = Wt[wcur] + wgbase;
#pragma unroll
            for (int i = 0; i < 16; i++) {
                int b = wid * 16 + i;
                float w = 0.f;
                if (mreg[i]) w = (s2v >= sT[b]) ? sP[b] * pv : sQ[b] * qv;
                sts16(wa, __half_as_ushort(__float2half_rn(w)));
                wa += ST;
            }
        }
        // stage tile t+1 (mask + n-scalars) into regs
        if (t + 1 < NT) {
            const int* mb2 = mbase + (t + 1) * KT;
#pragma unroll
            for (int i = 0; i < 16; i++) mreg[i] = mb2[(size_t)i * N_COLS];
            int n = nbase + (t + 1) * KT + lane;
            pv = g_p[n]; qv = g_q[n]; s2v = g_s2[n];
        }
        // ensure h tile t arrived (allow t+1 in flight)
        if (t + 1 < NT) asm volatile("cp.async.wait_group 1;");
        else            asm volatile("cp.async.wait_group 0;");
        __syncthreads();  // Wt[wcur] + Ht[hbi] ready; prior MMA done

        // prefetch h tile t+2 into the buffer MMA(t-1) just finished with
        if (t + 2 < NT) {
            int nb = (t + 2) % 3;
            const __half* src = hsrc + (t + 2) * KT;
            cpa16(Ht[nb] + hstore, src);
            cpa16(Ht[nb] + hstore + 16, src + 8);
            asm volatile("cp.async.commit_group;");
        }

        // MMA phase: 2 j x (2 mb x 8 fb) = 32 HMMA m16n8k16
        const uint32_t wbase = Wt[wcur] + wmma0;
        const uint32_t hbase = Ht[hbi] + hmma0;
#pragma unroll
        for (int j = 0; j < 2; j++) {
            uint32_t a[2][4];
#pragma unroll
            for (int mb = 0; mb < 2; mb++) {
                uint32_t a0 = wbase + mb * 16 * ST + j * 32;
                a[mb][0] = lds32(a0);
                a[mb][1] = lds32(a0 + 8 * ST);
                a[mb][2] = lds32(a0 + 16);
                a[mb][3] = lds32(a0 + 8 * ST + 16);
            }
#pragma unroll
            for (int fb = 0; fb < 8; fb++) {
                uint32_t h0 = hbase + fb * 8 * ST + j * 32;
                uint32_t b0 = lds32(h0);
                uint32_t b1 = lds32(h0 + 16);
                mma_f16(d[0][fb], a[0], b0, b1);
                mma_f16(d[1][fb], a[1], b0, b1);
            }
        }
        hbi = (hbi + 1) % 3;
    }

    // epilogue: write partials
    float* pbase = g_part + (size_t)blockIdx.y * B_ROWS * OUT_DIM;
#pragma unroll
    for (int mb = 0; mb < 2; mb++) {
        int brow = gb0 + bwarp * 32 + mb * 16 + qr;
#pragma unroll
        for (int fb = 0; fb < 8; fb++) {
            int f = fwarp * 64 + fb * 8 + qc * 2;
            float* p0 = pbase + (size_t)brow * OUT_DIM + f;
            *(float2*)p0 = make_float2(d[mb][fb][0], d[mb][fb][1]);
            *(float2*)(p0 + 8 * OUT_DIM) = make_float2(d[mb][fb][2], d[mb][fb][3]);
        }
    }
}

// ---------------- K5: reduce partials + L2 normalize ----------------
__global__ __launch_bounds__(128) void k_finish(float* __restrict__ out) {
    __shared__ float red[4];
    int b = blockIdx.x, f = threadIdx.x;
    float s = 0.f;
#pragma unroll
    for (int k = 0; k < NSPLIT; k++)
        s += g_part[((size_t)k * B_ROWS + b) * OUT_DIM + f];
    float ss = s * s;
#pragma unroll
    for (int o = 16; o; o >>= 1) ss += __shfl_xor_sync(0xffffffffu, ss, o);
    if ((f & 31) == 0) red[f >> 5] = ss;
    __syncthreads();
    float tot = red[0] + red[1] + red[2] + red[3];
    out[b * OUT_DIM + f] = s / fmaxf(sqrtf(tot), 1e-12f);
}

// ---------------- launch ----------------
extern "C" void kernel_launch(void* const* d_in, const int* in_sizes, int n_in,
                              void* d_out, int out_size) {
    const float* gf    = (const float*)d_in[0];  // [100000, 256]
    const int*   nodes = (const int*)d_in[1];    // [4096]
    const int*   un    = (const int*)d_in[2];    // [8192]
    const int*   mask  = (const int*)d_in[3];    // [4096, 8192]
    const float* W     = (const float*)d_in[4];  // [256, 128]
    const float* a1    = (const float*)d_in[5];  // [128]
    const float* a2    = (const float*)d_in[6];  // [128]
    float* out = (float*)d_out;                  // [4096, 128]

    static int smem_set = 0;
    const int SMEM = 51200 + 3 * 128 * 4;  // 2xWt + 3xHt + sT/sP/sQ = 52736
    if (!smem_set) {
        cudaFuncSetAttribute(k_main, cudaFuncAttributeMaxDynamicSharedMemorySize, SMEM);
        smem_set = 1;
    }

    k_wa1<<<1, 256>>>(W, a1);
    k_hneigh<<<N_COLS / 32, 256>>>(gf, un, W, a2);
    k_sm<<<1, 1024>>>();
    k_rowb<<<B_ROWS / 8, 256>>>(gf, nodes);
    k_main<<<dim3(B_ROWS / 128, NSPLIT), 256, SMEM>>>(mask);
    k_finish<<<B_ROWS, 128>>>(out);
}